// round 8
// baseline (speedup 1.0000x reference)
#include <cuda_runtime.h>
#include <math.h>

#define NE      50000
#define DIM     64
#define NREL    400
#define NLAYERS 3
#define BS      4
#define NEDGE   400000
#define MAXSLOTS (BS * NE)
#define FULL 0xffffffffu
#define TPB 256
#define WPB (TPB / 32)

// ---------------- persistent device scratch (static, no allocation) ----------
// Zero-initialized at module load; the epilogue restores zero state for every
// entry it dirtied, so each graph replay starts clean.
__device__ float        g_h[MAXSLOTS * DIM];
__device__ float        g_agg[MAXSLOTS * DIM];
__device__ int          g_slotmap[BS * NE];      // slot+1, 0 = free, -1 = claiming
__device__ unsigned int g_mask[NE];              // bit b = (b,node) active
__device__ int          g_elist[BS * NEDGE];     // packed (edge<<2)|b
__device__ int          g_nlist[MAXSLOTS];       // packed (node<<2)|b
__device__ int          g_cnt[8];                // 0 slots, 1 nlist, 2+l edges/layer
__device__ unsigned int g_bar[8];                // device barrier counters

struct SMemMsg { float M[DIM * DIM]; float G[DIM * DIM]; float sh[WPB][DIM]; };
struct SMemUpd { float W[2 * DIM * DIM]; float x[WPB][2 * DIM]; };
struct SMemSc  { float2 w[2 * DIM * 32]; float4 te4[WPB][DIM]; };   // 32KB + 8KB
union SMemAll { SMemMsg m; SMemUpd u; SMemSc s; };

// Grid-wide barrier: grid sized by the occupancy API -> all blocks resident.
__device__ __forceinline__ void gbar(int i) {
    __syncthreads();
    if (threadIdx.x == 0) {
        __threadfence();
        atomicAdd(&g_bar[i], 1u);
        while (*(volatile unsigned int*)&g_bar[i] < gridDim.x) __nanosleep(32);
    }
    __syncthreads();
}

// Warp-aggregated append of active (edge,batch) pairs into g_elist.
__device__ __forceinline__ void push4(int base, const unsigned mm[4], int cslot, int lane) {
    int cnt = __popc(mm[0]) + __popc(mm[1]) + __popc(mm[2]) + __popc(mm[3]);
    int x = cnt;
    #pragma unroll
    for (int o = 1; o < 32; o <<= 1) {
        int y = __shfl_up_sync(FULL, x, o);
        if (lane >= o) x += y;
    }
    int warpTotal = __shfl_sync(FULL, x, 31);
    if (warpTotal == 0) return;
    int basePos = 0;
    if (lane == 31) basePos = atomicAdd(&g_cnt[cslot], warpTotal);
    basePos = __shfl_sync(FULL, basePos, 31);
    int pos = basePos + x - cnt;
    #pragma unroll
    for (int j = 0; j < 4; j++) {
        unsigned m = mm[j];
        while (m) {
            int b = __ffs((int)m) - 1;
            m &= m - 1;
            g_elist[pos++] = ((base + j) << 2) | b;
        }
    }
}

__device__ __forceinline__ void scan_layer(const int* __restrict__ esrc, int layer,
                                           int gwarp, int gwarps, int lane) {
    const int CW = NEDGE / 4 / 32;   // 3125
    for (int cw = gwarp; cw < CW; cw += gwarps) {
        int base = (cw * 32 + lane) * 4;
        int4 e4 = *reinterpret_cast<const int4*>(esrc + base);
        unsigned mm[4];
        mm[0] = __ldcg(&g_mask[e4.x]);
        mm[1] = __ldcg(&g_mask[e4.y]);
        mm[2] = __ldcg(&g_mask[e4.z]);
        mm[3] = __ldcg(&g_mask[e4.w]);
        push4(base, mm, 2 + layer, lane);
    }
}

__global__ void __launch_bounds__(TPB, 2)
k_all(const float* __restrict__ ent, const float* __restrict__ qemb,
      const float* __restrict__ rele, const float* __restrict__ msgW,
      const float* __restrict__ gateW, const float* __restrict__ updW,
      const float* __restrict__ updb, const float* __restrict__ lng,
      const float* __restrict__ lnb, const float* __restrict__ sW1,
      const float* __restrict__ sb1, const float* __restrict__ sW2,
      const float* __restrict__ sb2, const int* __restrict__ source,
      const int* __restrict__ qrel, const int* __restrict__ esrc,
      const int* __restrict__ etgt, const int* __restrict__ erel,
      float* __restrict__ out) {
    __shared__ SMemAll sm;
    const int tid  = threadIdx.x;
    const int lane = tid & 31;
    const int wl   = tid >> 5;
    const int bid  = blockIdx.x;
    const int nb   = gridDim.x;
    const int gwarps = (nb * TPB) >> 5;
    const int gwarp  = bid * WPB + wl;

    // ---------------- P0: scan layer-0 (vs source ids) + seed ----------------
    {
        int s0 = __ldg(&source[0]), s1 = __ldg(&source[1]);
        int s2 = __ldg(&source[2]), s3 = __ldg(&source[3]);
        const int CW = NEDGE / 4 / 32;
        for (int cw = gwarp; cw < CW; cw += gwarps) {
            int base = (cw * 32 + lane) * 4;
            int4 e4 = *reinterpret_cast<const int4*>(esrc + base);
            unsigned mm[4];
            mm[0] = (unsigned)(e4.x == s0) | ((unsigned)(e4.x == s1) << 1) |
                    ((unsigned)(e4.x == s2) << 2) | ((unsigned)(e4.x == s3) << 3);
            mm[1] = (unsigned)(e4.y == s0) | ((unsigned)(e4.y == s1) << 1) |
                    ((unsigned)(e4.y == s2) << 2) | ((unsigned)(e4.y == s3) << 3);
            mm[2] = (unsigned)(e4.z == s0) | ((unsigned)(e4.z == s1) << 1) |
                    ((unsigned)(e4.z == s2) << 2) | ((unsigned)(e4.z == s3) << 3);
            mm[3] = (unsigned)(e4.w == s0) | ((unsigned)(e4.w == s1) << 1) |
                    ((unsigned)(e4.w == s2) << 2) | ((unsigned)(e4.w == s3) << 3);
            push4(base, mm, 2, lane);
        }
        if (bid == 0) {
            if (wl < BS) {
                int n = __ldg(&source[wl]);
                int r = __ldg(&qrel[wl]);
                if (lane == 0) {
                    g_slotmap[wl * NE + n] = wl + 1;
                    atomicOr(&g_mask[n], 1u << wl);
                    g_nlist[wl] = (n << 2) | wl;
                }
                g_h[wl * DIM + lane]      = __ldg(&ent[n * DIM + lane])      + __ldg(&qemb[r * DIM + lane]);
                g_h[wl * DIM + lane + 32] = __ldg(&ent[n * DIM + lane + 32]) + __ldg(&qemb[r * DIM + lane + 32]);
                g_agg[wl * DIM + lane] = 0.f;
                g_agg[wl * DIM + lane + 32] = 0.f;
            }
            if (tid == 0) { g_cnt[0] = BS; g_cnt[1] = BS; }
        }
    }
    gbar(0);

    // ---------------- per-layer: msg, then (scan next + update) ----------------
    for (int l = 0; l < NLAYERS; l++) {
        // ---- msg(l): claim target slots + matvec + atomic scatter ----
        {
            int total = __ldcg(&g_cnt[2 + l]);
            int pb = min(min(nb, 128), max(1, (total + WPB - 1) / WPB));
            if (bid < pb) {
                for (int i = tid; i < DIM * DIM; i += TPB) {
                    sm.m.M[i] = __ldg(&msgW[l * DIM * DIM + i]);
                    sm.m.G[i] = __ldg(&gateW[l * DIM * DIM + i]);
                }
                __syncthreads();
                for (int idx = bid * WPB + wl; idx < total; idx += pb * WPB) {
                    int p = __ldcg(&g_elist[idx]);
                    int e = p >> 2, b = p & 3;
                    int s = __ldg(&esrc[e]), t = __ldg(&etgt[e]), r = __ldg(&erel[e]);
                    int ss = __ldcg(&g_slotmap[b * NE + s]) - 1;

                    int* sp = &g_slotmap[b * NE + t];
                    int cur;
                    if (lane == 0) cur = atomicCAS(sp, 0, -1);
                    cur = __shfl_sync(FULL, cur, 0);
                    int ts;
                    if (cur == 0) {                       // claimed: init slot
                        int slot;
                        if (lane == 0) slot = atomicAdd(&g_cnt[0], 1);
                        slot = __shfl_sync(FULL, slot, 0);
                        g_h[slot * DIM + lane] = 0.f;       g_h[slot * DIM + lane + 32] = 0.f;
                        g_agg[slot * DIM + lane] = 0.f;     g_agg[slot * DIM + lane + 32] = 0.f;
                        __syncwarp();
                        __threadfence();
                        if (lane == 0) {
                            int ni = atomicAdd(&g_cnt[1], 1);
                            g_nlist[ni] = (t << 2) | b;
                            atomicOr(&g_mask[t], 1u << b);  // activation for next scan
                            atomicExch(sp, slot + 1);       // publish
                        }
                        ts = slot;
                    } else if (cur > 0) {
                        ts = cur - 1;
                    } else {
                        if (lane == 0) { do { cur = atomicAdd(sp, 0); } while (cur <= 0); }
                        cur = __shfl_sync(FULL, cur, 0);
                        ts = cur - 1;
                    }

                    sm.m.sh[wl][lane]      = __ldcg(&g_h[ss * DIM + lane]);
                    sm.m.sh[wl][lane + 32] = __ldcg(&g_h[ss * DIM + lane + 32]);
                    __syncwarp();
                    float m0 = 0.f, m1 = 0.f, q0 = 0.f, q1 = 0.f;
                    #pragma unroll 8
                    for (int k = 0; k < DIM; k++) {
                        float hk = sm.m.sh[wl][k];
                        m0 = fmaf(hk, sm.m.M[k * DIM + lane],      m0);
                        m1 = fmaf(hk, sm.m.M[k * DIM + lane + 32], m1);
                        q0 = fmaf(hk, sm.m.G[k * DIM + lane],      q0);
                        q1 = fmaf(hk, sm.m.G[k * DIM + lane + 32], q1);
                    }
                    const float* rr = rele + (size_t)(l * NREL + r) * DIM;
                    float v0 = __ldg(&rr[lane])      * m0 * (1.f / (1.f + expf(-q0)));
                    float v1 = __ldg(&rr[lane + 32]) * m1 * (1.f / (1.f + expf(-q1)));
                    atomicAdd(&g_agg[ts * DIM + lane],      v0);
                    atomicAdd(&g_agg[ts * DIM + lane + 32], v1);
                    __syncwarp();
                }
            }
        }
        gbar(1 + 2 * l);

        // ---- scan(l+1) over all blocks (independent of update) ----
        if (l + 1 < NLAYERS) scan_layer(esrc, l + 1, gwarp, gwarps, lane);

        // ---- update(l): h = LN(h + relu([h,agg]@W + b)) over nlist ----
        {
            int total = __ldcg(&g_cnt[1]);
            int pb = min(min(nb, 128), max(1, (total + WPB - 1) / WPB));
            if (bid < pb) {
                for (int i = tid; i < 2 * DIM * DIM; i += TPB)
                    sm.u.W[i] = __ldg(&updW[l * 2 * DIM * DIM + i]);
                __syncthreads();
                float ub0 = __ldg(&updb[l * DIM + lane]), ub1 = __ldg(&updb[l * DIM + lane + 32]);
                float lg0 = __ldg(&lng[l * DIM + lane]),  lg1 = __ldg(&lng[l * DIM + lane + 32]);
                float lb0 = __ldg(&lnb[l * DIM + lane]),  lb1 = __ldg(&lnb[l * DIM + lane + 32]);
                for (int idx = bid * WPB + wl; idx < total; idx += pb * WPB) {
                    int p = __ldcg(&g_nlist[idx]);
                    int n = p >> 2, b = p & 3;
                    int slot = __ldcg(&g_slotmap[b * NE + n]) - 1;
                    float h0 = __ldcg(&g_h[slot * DIM + lane]);
                    float h1 = __ldcg(&g_h[slot * DIM + lane + 32]);
                    float a0 = __ldcg(&g_agg[slot * DIM + lane]);
                    float a1 = __ldcg(&g_agg[slot * DIM + lane + 32]);
                    sm.u.x[wl][lane] = h0;      sm.u.x[wl][lane + 32] = h1;
                    sm.u.x[wl][64 + lane] = a0; sm.u.x[wl][96 + lane] = a1;
                    __syncwarp();
                    float u0 = ub0, u1 = ub1;
                    #pragma unroll 8
                    for (int k = 0; k < 2 * DIM; k++) {
                        float xk = sm.u.x[wl][k];
                        u0 = fmaf(xk, sm.u.W[k * DIM + lane],      u0);
                        u1 = fmaf(xk, sm.u.W[k * DIM + lane + 32], u1);
                    }
                    u0 = fmaxf(u0, 0.f); u1 = fmaxf(u1, 0.f);
                    float x0 = h0 + u0, x1 = h1 + u1;
                    float sums = x0 + x1;
                    #pragma unroll
                    for (int o = 16; o > 0; o >>= 1) sums += __shfl_xor_sync(FULL, sums, o);
                    float mean = sums * (1.f / 64.f);
                    float d0 = x0 - mean, d1 = x1 - mean;
                    float v = d0 * d0 + d1 * d1;
                    #pragma unroll
                    for (int o = 16; o > 0; o >>= 1) v += __shfl_xor_sync(FULL, v, o);
                    float inv = rsqrtf(v * (1.f / 64.f) + 1e-5f);
                    g_h[slot * DIM + lane]      = d0 * inv * lg0 + lb0;
                    g_h[slot * DIM + lane + 32] = d1 * inv * lg1 + lb1;
                    g_agg[slot * DIM + lane] = 0.f;
                    g_agg[slot * DIM + lane + 32] = 0.f;
                    __syncwarp();
                }
            }
        }
        gbar(2 + 2 * l);
    }

    // ---------------- score ----------------
    {
        for (int i = tid; i < 2 * DIM * 32; i += TPB) {
            int k = i >> 5, j = i & 31;
            sm.s.w[i] = make_float2(__ldg(&sW1[k * DIM + j]), __ldg(&sW1[k * DIM + j + 32]));
        }
        __syncthreads();
        float rb0 = __ldg(&sb1[lane]), rb1 = __ldg(&sb1[lane + 32]);
        float rv0 = __ldg(&sW2[lane]), rv1 = __ldg(&sW2[lane + 32]);
        float b2 = __ldg(&sb2[0]);
        int nAct = __ldcg(&g_cnt[1]);
        const int nBg = NE / 4;       // 12500
        int W = nBg + nAct;
        float4* te4 = sm.s.te4[wl];
        for (int w = gwarp; w < W; w += gwarps) {
            if (w < nBg) {
                // ---- background: 4 nodes, h = 0 → only rows [64,128) of sW1 ----
                int n0 = w * 4;
                int4 mload;
                if (lane == 0) mload = __ldcg(reinterpret_cast<const int4*>(&g_mask[n0]));
                float v0 = __ldg(&ent[(n0 + 0) * DIM + lane]);
                float v1 = __ldg(&ent[(n0 + 1) * DIM + lane]);
                float v2 = __ldg(&ent[(n0 + 2) * DIM + lane]);
                float v3 = __ldg(&ent[(n0 + 3) * DIM + lane]);
                float u0 = __ldg(&ent[(n0 + 0) * DIM + lane + 32]);
                float u1 = __ldg(&ent[(n0 + 1) * DIM + lane + 32]);
                float u2 = __ldg(&ent[(n0 + 2) * DIM + lane + 32]);
                float u3 = __ldg(&ent[(n0 + 3) * DIM + lane + 32]);
                // transposed staging: te4[k] = 4 nodes' column-k values
                // → inner loop reads are broadcast LDS.128, conflict-free
                te4[lane]      = make_float4(v0, v1, v2, v3);
                te4[lane + 32] = make_float4(u0, u1, u2, u3);
                __syncwarp();
                float s0[4], s1[4];
                #pragma unroll
                for (int j = 0; j < 4; j++) { s0[j] = rb0; s1[j] = rb1; }
                #pragma unroll 8
                for (int k = 0; k < DIM; k++) {
                    float2 wv = sm.s.w[(DIM + k) * 32 + lane];
                    float4 t = te4[k];
                    s0[0] = fmaf(t.x, wv.x, s0[0]); s1[0] = fmaf(t.x, wv.y, s1[0]);
                    s0[1] = fmaf(t.y, wv.x, s0[1]); s1[1] = fmaf(t.y, wv.y, s1[1]);
                    s0[2] = fmaf(t.z, wv.x, s0[2]); s1[2] = fmaf(t.z, wv.y, s1[2]);
                    s0[3] = fmaf(t.w, wv.x, s0[3]); s1[3] = fmaf(t.w, wv.y, s1[3]);
                }
                #pragma unroll
                for (int j = 0; j < 4; j++) {
                    float a = fmaxf(s0[j], 0.f) * rv0 + fmaxf(s1[j], 0.f) * rv1;
                    #pragma unroll
                    for (int o = 16; o > 0; o >>= 1) a += __shfl_xor_sync(FULL, a, o);
                    if (lane == 0) {
                        int n = n0 + j;
                        float sc = a + b2;
                        unsigned m = (j == 0) ? (unsigned)mload.x :
                                     (j == 1) ? (unsigned)mload.y :
                                     (j == 2) ? (unsigned)mload.z : (unsigned)mload.w;
                        if (!(m & 1u)) out[0 * NE + n] = sc;
                        if (!(m & 2u)) out[1 * NE + n] = sc;
                        if (!(m & 4u)) out[2 * NE + n] = sc;
                        if (!(m & 8u)) out[3 * NE + n] = sc;
                    }
                }
                __syncwarp();
            } else {
                // ---- active (b,n): full [h, te] @ sW1 ----
                int p = __ldcg(&g_nlist[w - nBg]);
                int n = p >> 2, b = p & 3;
                int slot = __ldcg(&g_slotmap[b * NE + n]) - 1;
                float* tep = reinterpret_cast<float*>(te4);   // 256-float scratch
                tep[lane]      = __ldcg(&g_h[slot * DIM + lane]);
                tep[lane + 32] = __ldcg(&g_h[slot * DIM + lane + 32]);
                tep[64 + lane] = __ldg(&ent[n * DIM + lane]);
                tep[96 + lane] = __ldg(&ent[n * DIM + lane + 32]);
                __syncwarp();
                float s0 = rb0, s1 = rb1;
                #pragma unroll 8
                for (int k = 0; k < 2 * DIM; k++) {
                    float xk = tep[k];
                    float2 wv = sm.s.w[k * 32 + lane];
                    s0 = fmaf(xk, wv.x, s0);
                    s1 = fmaf(xk, wv.y, s1);
                }
                float a = fmaxf(s0, 0.f) * rv0 + fmaxf(s1, 0.f) * rv1;
                #pragma unroll
                for (int o = 16; o > 0; o >>= 1) a += __shfl_xor_sync(FULL, a, o);
                if (lane == 0) out[b * NE + n] = a + b2;
                __syncwarp();
            }
        }
    }

    // ---------------- final arrive barrier + state cleanup (block 0) ----------
    __syncthreads();
    if (tid == 0) {
        __threadfence();
        atomicAdd(&g_bar[7], 1u);
    }
    if (bid == 0) {
        if (tid == 0) {
            while (*(volatile unsigned int*)&g_bar[7] < (unsigned)nb) __nanosleep(32);
        }
        __syncthreads();
        int total = __ldcg(&g_cnt[1]);
        for (int i = tid; i < total; i += TPB) {
            int p = __ldcg(&g_nlist[i]);
            int n = p >> 2, b = p & 3;
            g_slotmap[b * NE + n] = 0;
            g_mask[n] = 0u;            // duplicate writes (same n, diff b) are benign
        }
        __syncthreads();
        if (tid < 8) { g_cnt[tid] = 0; g_bar[tid] = 0u; }
    }
}

extern "C" void kernel_launch(void* const* d_in, const int* in_sizes, int n_in,
                              void* d_out, int out_size) {
    const float* ent   = (const float*)d_in[0];
    const float* qemb  = (const float*)d_in[1];
    const float* rele  = (const float*)d_in[2];
    const float* msgW  = (const float*)d_in[3];
    const float* gateW = (const float*)d_in[4];
    const float* updW  = (const float*)d_in[5];
    const float* updb  = (const float*)d_in[6];
    const float* lng   = (const float*)d_in[7];
    const float* lnb   = (const float*)d_in[8];
    const float* sW1   = (const float*)d_in[9];
    const float* sb1   = (const float*)d_in[10];
    const float* sW2   = (const float*)d_in[11];
    const float* sb2   = (const float*)d_in[12];
    const int* source  = (const int*)d_in[13];
    const int* qrel    = (const int*)d_in[14];
    const int* esrc    = (const int*)d_in[15];
    const int* etgt    = (const int*)d_in[16];
    const int* erel    = (const int*)d_in[17];
    float* out = (float*)d_out;

    // Grid sized to guaranteed-resident occupancy (barrier safety is structural).
    int dev = 0;
    cudaGetDevice(&dev);
    int sms = 0;
    cudaDeviceGetAttribute(&sms, cudaDevAttrMultiProcessorCount, dev);
    int maxb = 0;
    cudaOccupancyMaxActiveBlocksPerMultiprocessor(&maxb, k_all, TPB, 0);
    if (maxb < 1) maxb = 1;
    int grid = sms * maxb;

    k_all<<<grid, TPB>>>(ent, qemb, rele, msgW, gateW, updW, updb, lng, lnb,
                         sW1, sb1, sW2, sb2, source, qrel, esrc, etgt, erel, out);
}

// round 9
// speedup vs baseline: 1.1516x; 1.1516x over previous
#include <cuda_runtime.h>
#include <math.h>

#define NE      50000
#define DIM     64
#define NREL    400
#define NLAYERS 3
#define BS      4
#define NEDGE   400000
#define MAXSLOTS (BS * NE)
#define FULL 0xffffffffu
#define TPB 256
#define WPB (TPB / 32)

// ---------------- persistent device scratch (static, no allocation) ----------
__device__ float        g_h[MAXSLOTS * DIM];
__device__ float        g_agg[MAXSLOTS * DIM];
__device__ int          g_slotmap[BS * NE];      // slot+1, 0 = free, -1 = claiming
__device__ unsigned int g_mask[NE];              // bit b = (b,node) active
__device__ int          g_elist[BS * NEDGE];     // packed (edge<<2)|b
__device__ int          g_nlist[MAXSLOTS];       // packed (node<<2)|b
__device__ int          g_cnt[8];                // 0 slots, 1 nlist, 2+l edges/layer
__device__ unsigned int g_bar[16];               // device barrier counters

struct SMemMsg { float M[DIM * DIM]; float G[DIM * DIM]; float sh[WPB][DIM]; };
struct SMemUpd { float W[2 * DIM * DIM]; float x[WPB][2 * DIM]; };
struct SMemSc  { float2 w[2 * DIM * 32]; float te[WPB][4 * DIM]; };
union SMemAll { SMemMsg m; SMemUpd u; SMemSc s; };

// Grid-wide barrier: grid sized by the occupancy API -> all blocks resident.
__device__ __forceinline__ void gbar(int i) {
    __syncthreads();
    if (threadIdx.x == 0) {
        __threadfence();
        atomicAdd(&g_bar[i], 1u);
        while (*(volatile unsigned int*)&g_bar[i] < gridDim.x) __nanosleep(32);
    }
    __syncthreads();
}

// Warp-aggregated append of active (edge,batch) pairs into g_elist.
__device__ __forceinline__ void push4(int base, const unsigned mm[4], int cslot, int lane) {
    int cnt = __popc(mm[0]) + __popc(mm[1]) + __popc(mm[2]) + __popc(mm[3]);
    int x = cnt;
    #pragma unroll
    for (int o = 1; o < 32; o <<= 1) {
        int y = __shfl_up_sync(FULL, x, o);
        if (lane >= o) x += y;
    }
    int warpTotal = __shfl_sync(FULL, x, 31);
    if (warpTotal == 0) return;
    int basePos = 0;
    if (lane == 31) basePos = atomicAdd(&g_cnt[cslot], warpTotal);
    basePos = __shfl_sync(FULL, basePos, 31);
    int pos = basePos + x - cnt;
    #pragma unroll
    for (int j = 0; j < 4; j++) {
        unsigned m = mm[j];
        while (m) {
            int b = __ffs((int)m) - 1;
            m &= m - 1;
            g_elist[pos++] = ((base + j) << 2) | b;
        }
    }
}

__device__ __forceinline__ void scan_layer(const int* __restrict__ esrc, int layer,
                                           int gwarp, int gwarps, int lane) {
    const int CW = NEDGE / 4 / 32;   // 3125
    for (int cw = gwarp; cw < CW; cw += gwarps) {
        int base = (cw * 32 + lane) * 4;
        int4 e4 = *reinterpret_cast<const int4*>(esrc + base);
        unsigned mm[4];
        mm[0] = __ldcg(&g_mask[e4.x]);
        mm[1] = __ldcg(&g_mask[e4.y]);
        mm[2] = __ldcg(&g_mask[e4.z]);
        mm[3] = __ldcg(&g_mask[e4.w]);
        push4(base, mm, 2 + layer, lane);
    }
}

__global__ void __launch_bounds__(TPB, 2)
k_all(const float* __restrict__ ent, const float* __restrict__ qemb,
      const float* __restrict__ rele, const float* __restrict__ msgW,
      const float* __restrict__ gateW, const float* __restrict__ updW,
      const float* __restrict__ updb, const float* __restrict__ lng,
      const float* __restrict__ lnb, const float* __restrict__ sW1,
      const float* __restrict__ sb1, const float* __restrict__ sW2,
      const float* __restrict__ sb2, const int* __restrict__ source,
      const int* __restrict__ qrel, const int* __restrict__ esrc,
      const int* __restrict__ etgt, const int* __restrict__ erel,
      float* __restrict__ out) {
    __shared__ SMemAll sm;
    const int tid  = threadIdx.x;
    const int lane = tid & 31;
    const int wl   = tid >> 5;
    const int bid  = blockIdx.x;
    const int nb   = gridDim.x;
    const int gthreads = nb * TPB;
    const int gwarps   = gthreads >> 5;
    const int gwarp    = bid * WPB + wl;
    const int gt       = bid * TPB + tid;

    // ---------------- P0: zero slotmap+mask  ∥  scan layer-0 ----------------
    // Disjoint state: zeroing writes slotmap/mask; scan-0 compares esrc against
    // the source ids in registers and writes elist/cnt[2] only.
    {
        int4 z = make_int4(0, 0, 0, 0);
        for (int j = gt; j < BS * NE / 4; j += gthreads) ((int4*)g_slotmap)[j] = z;
        for (int j = gt; j < NE / 4; j += gthreads) ((int4*)g_mask)[j] = z;

        int s0 = __ldg(&source[0]), s1 = __ldg(&source[1]);
        int s2 = __ldg(&source[2]), s3 = __ldg(&source[3]);
        const int CW = NEDGE / 4 / 32;
        for (int cw = gwarp; cw < CW; cw += gwarps) {
            int base = (cw * 32 + lane) * 4;
            int4 e4 = *reinterpret_cast<const int4*>(esrc + base);
            unsigned mm[4];
            mm[0] = (unsigned)(e4.x == s0) | ((unsigned)(e4.x == s1) << 1) |
                    ((unsigned)(e4.x == s2) << 2) | ((unsigned)(e4.x == s3) << 3);
            mm[1] = (unsigned)(e4.y == s0) | ((unsigned)(e4.y == s1) << 1) |
                    ((unsigned)(e4.y == s2) << 2) | ((unsigned)(e4.y == s3) << 3);
            mm[2] = (unsigned)(e4.z == s0) | ((unsigned)(e4.z == s1) << 1) |
                    ((unsigned)(e4.z == s2) << 2) | ((unsigned)(e4.z == s3) << 3);
            mm[3] = (unsigned)(e4.w == s0) | ((unsigned)(e4.w == s1) << 1) |
                    ((unsigned)(e4.w == s2) << 2) | ((unsigned)(e4.w == s3) << 3);
            push4(base, mm, 2, lane);
        }
    }
    gbar(0);

    // ---------------- P1: seed the BS source nodes (block 0 only) -------------
    if (bid == 0) {
        if (wl < BS) {
            int n = __ldg(&source[wl]);
            int r = __ldg(&qrel[wl]);
            if (lane == 0) {
                g_slotmap[wl * NE + n] = wl + 1;
                atomicOr(&g_mask[n], 1u << wl);
                g_nlist[wl] = (n << 2) | wl;
            }
            g_h[wl * DIM + lane]      = __ldg(&ent[n * DIM + lane])      + __ldg(&qemb[r * DIM + lane]);
            g_h[wl * DIM + lane + 32] = __ldg(&ent[n * DIM + lane + 32]) + __ldg(&qemb[r * DIM + lane + 32]);
            g_agg[wl * DIM + lane] = 0.f;
            g_agg[wl * DIM + lane + 32] = 0.f;
        }
        if (tid == 0) { g_cnt[0] = BS; g_cnt[1] = BS; }
    }
    gbar(1);

    // ---------------- per-layer: msg, then (scan next + update) ----------------
    for (int l = 0; l < NLAYERS; l++) {
        // ---- msg(l): claim target slots + matvec + atomic scatter ----
        {
            int total = __ldcg(&g_cnt[2 + l]);
            int pb = min(nb, (total + WPB - 1) / WPB);
            if (bid < pb) {
                for (int i = tid; i < DIM * DIM; i += TPB) {
                    sm.m.M[i] = __ldg(&msgW[l * DIM * DIM + i]);
                    sm.m.G[i] = __ldg(&gateW[l * DIM * DIM + i]);
                }
                __syncthreads();
                for (int idx = bid * WPB + wl; idx < total; idx += pb * WPB) {
                    int p = __ldcg(&g_elist[idx]);
                    int e = p >> 2, b = p & 3;
                    int s = __ldg(&esrc[e]), t = __ldg(&etgt[e]), r = __ldg(&erel[e]);
                    int ss = __ldcg(&g_slotmap[b * NE + s]) - 1;

                    int* sp = &g_slotmap[b * NE + t];
                    int cur;
                    if (lane == 0) cur = atomicCAS(sp, 0, -1);
                    cur = __shfl_sync(FULL, cur, 0);
                    int ts;
                    if (cur == 0) {                       // claimed: init slot
                        int slot;
                        if (lane == 0) slot = atomicAdd(&g_cnt[0], 1);
                        slot = __shfl_sync(FULL, slot, 0);
                        g_h[slot * DIM + lane] = 0.f;       g_h[slot * DIM + lane + 32] = 0.f;
                        g_agg[slot * DIM + lane] = 0.f;     g_agg[slot * DIM + lane + 32] = 0.f;
                        __syncwarp();
                        __threadfence();
                        if (lane == 0) {
                            int ni = atomicAdd(&g_cnt[1], 1);
                            g_nlist[ni] = (t << 2) | b;
                            atomicOr(&g_mask[t], 1u << b);  // activation for next scan
                            atomicExch(sp, slot + 1);       // publish
                        }
                        ts = slot;
                    } else if (cur > 0) {
                        ts = cur - 1;
                    } else {
                        if (lane == 0) { do { cur = atomicAdd(sp, 0); } while (cur <= 0); }
                        cur = __shfl_sync(FULL, cur, 0);
                        ts = cur - 1;
                    }

                    sm.m.sh[wl][lane]      = __ldcg(&g_h[ss * DIM + lane]);
                    sm.m.sh[wl][lane + 32] = __ldcg(&g_h[ss * DIM + lane + 32]);
                    __syncwarp();
                    float m0 = 0.f, m1 = 0.f, q0 = 0.f, q1 = 0.f;
                    #pragma unroll 8
                    for (int k = 0; k < DIM; k++) {
                        float hk = sm.m.sh[wl][k];
                        m0 = fmaf(hk, sm.m.M[k * DIM + lane],      m0);
                        m1 = fmaf(hk, sm.m.M[k * DIM + lane + 32], m1);
                        q0 = fmaf(hk, sm.m.G[k * DIM + lane],      q0);
                        q1 = fmaf(hk, sm.m.G[k * DIM + lane + 32], q1);
                    }
                    const float* rr = rele + (size_t)(l * NREL + r) * DIM;
                    float v0 = __ldg(&rr[lane])      * m0 * (1.f / (1.f + expf(-q0)));
                    float v1 = __ldg(&rr[lane + 32]) * m1 * (1.f / (1.f + expf(-q1)));
                    atomicAdd(&g_agg[ts * DIM + lane],      v0);
                    atomicAdd(&g_agg[ts * DIM + lane + 32], v1);
                    __syncwarp();
                }
            }
        }
        gbar(2 + 2 * l);

        // ---- scan(l+1) over all blocks (independent of update) ----
        if (l + 1 < NLAYERS) scan_layer(esrc, l + 1, gwarp, gwarps, lane);

        // ---- update(l): h = LN(h + relu([h,agg]@W + b)) over nlist ----
        {
            int total = __ldcg(&g_cnt[1]);
            int pb = min(nb, (total + WPB - 1) / WPB);
            if (bid < pb) {
                for (int i = tid; i < 2 * DIM * DIM; i += TPB)
                    sm.u.W[i] = __ldg(&updW[l * 2 * DIM * DIM + i]);
                __syncthreads();
                float ub0 = __ldg(&updb[l * DIM + lane]), ub1 = __ldg(&updb[l * DIM + lane + 32]);
                float lg0 = __ldg(&lng[l * DIM + lane]),  lg1 = __ldg(&lng[l * DIM + lane + 32]);
                float lb0 = __ldg(&lnb[l * DIM + lane]),  lb1 = __ldg(&lnb[l * DIM + lane + 32]);
                for (int idx = bid * WPB + wl; idx < total; idx += pb * WPB) {
                    int p = __ldcg(&g_nlist[idx]);
                    int n = p >> 2, b = p & 3;
                    int slot = __ldcg(&g_slotmap[b * NE + n]) - 1;
                    float h0 = __ldcg(&g_h[slot * DIM + lane]);
                    float h1 = __ldcg(&g_h[slot * DIM + lane + 32]);
                    float a0 = __ldcg(&g_agg[slot * DIM + lane]);
                    float a1 = __ldcg(&g_agg[slot * DIM + lane + 32]);
                    sm.u.x[wl][lane] = h0;      sm.u.x[wl][lane + 32] = h1;
                    sm.u.x[wl][64 + lane] = a0; sm.u.x[wl][96 + lane] = a1;
                    __syncwarp();
                    float u0 = ub0, u1 = ub1;
                    #pragma unroll 8
                    for (int k = 0; k < 2 * DIM; k++) {
                        float xk = sm.u.x[wl][k];
                        u0 = fmaf(xk, sm.u.W[k * DIM + lane],      u0);
                        u1 = fmaf(xk, sm.u.W[k * DIM + lane + 32], u1);
                    }
                    u0 = fmaxf(u0, 0.f); u1 = fmaxf(u1, 0.f);
                    float x0 = h0 + u0, x1 = h1 + u1;
                    float sums = x0 + x1;
                    #pragma unroll
                    for (int o = 16; o > 0; o >>= 1) sums += __shfl_xor_sync(FULL, sums, o);
                    float mean = sums * (1.f / 64.f);
                    float d0 = x0 - mean, d1 = x1 - mean;
                    float v = d0 * d0 + d1 * d1;
                    #pragma unroll
                    for (int o = 16; o > 0; o >>= 1) v += __shfl_xor_sync(FULL, v, o);
                    float inv = rsqrtf(v * (1.f / 64.f) + 1e-5f);
                    g_h[slot * DIM + lane]      = d0 * inv * lg0 + lb0;
                    g_h[slot * DIM + lane + 32] = d1 * inv * lg1 + lb1;
                    g_agg[slot * DIM + lane] = 0.f;
                    g_agg[slot * DIM + lane + 32] = 0.f;
                    __syncwarp();
                }
            }
        }
        gbar(3 + 2 * l);
    }

    // ---------------- score ----------------
    {
        for (int i = tid; i < 2 * DIM * 32; i += TPB) {
            int k = i >> 5, j = i & 31;
            sm.s.w[i] = make_float2(__ldg(&sW1[k * DIM + j]), __ldg(&sW1[k * DIM + j + 32]));
        }
        __syncthreads();
        float rb0 = __ldg(&sb1[lane]), rb1 = __ldg(&sb1[lane + 32]);
        float rv0 = __ldg(&sW2[lane]), rv1 = __ldg(&sW2[lane + 32]);
        float b2 = __ldg(&sb2[0]);
        int nAct = __ldcg(&g_cnt[1]);
        const int nBg = NE / 4;       // 12500
        int W = nBg + nAct;
        for (int w = gwarp; w < W; w += gwarps) {
            if (w < nBg) {
                // ---- background: 4 nodes, h = 0 → only rows [64,128) of sW1 ----
                int n0 = w * 4;
                int4 mload;
                if (lane == 0) mload = __ldcg(reinterpret_cast<const int4*>(&g_mask[n0]));
                #pragma unroll
                for (int j = 0; j < 4; j++) {
                    sm.s.te[wl][j * DIM + lane]      = __ldg(&ent[(n0 + j) * DIM + lane]);
                    sm.s.te[wl][j * DIM + lane + 32] = __ldg(&ent[(n0 + j) * DIM + lane + 32]);
                }
                __syncwarp();
                float s0[4], s1[4];
                #pragma unroll
                for (int j = 0; j < 4; j++) { s0[j] = rb0; s1[j] = rb1; }
                #pragma unroll 4
                for (int k = 0; k < DIM; k++) {
                    float2 wv = sm.s.w[(DIM + k) * 32 + lane];
                    #pragma unroll
                    for (int j = 0; j < 4; j++) {
                        float t = sm.s.te[wl][j * DIM + k];
                        s0[j] = fmaf(t, wv.x, s0[j]);
                        s1[j] = fmaf(t, wv.y, s1[j]);
                    }
                }
                float sc[4];
                #pragma unroll
                for (int j = 0; j < 4; j++) {
                    float a = fmaxf(s0[j], 0.f) * rv0 + fmaxf(s1[j], 0.f) * rv1;
                    #pragma unroll
                    for (int o = 16; o > 0; o >>= 1) a += __shfl_xor_sync(FULL, a, o);
                    sc[j] = a + b2;
                }
                if (lane == 0) {
                    unsigned any = (unsigned)(mload.x | mload.y | mload.z | mload.w);
                    if (any == 0u) {
                        // fast path: all 4 nodes background in all batches -> 4x STG.128
                        float4 v4 = make_float4(sc[0], sc[1], sc[2], sc[3]);
                        *reinterpret_cast<float4*>(&out[0 * NE + n0]) = v4;
                        *reinterpret_cast<float4*>(&out[1 * NE + n0]) = v4;
                        *reinterpret_cast<float4*>(&out[2 * NE + n0]) = v4;
                        *reinterpret_cast<float4*>(&out[3 * NE + n0]) = v4;
                    } else {
                        unsigned mm[4];
                        mm[0] = (unsigned)mload.x; mm[1] = (unsigned)mload.y;
                        mm[2] = (unsigned)mload.z; mm[3] = (unsigned)mload.w;
                        #pragma unroll
                        for (int j = 0; j < 4; j++) {
                            int n = n0 + j;
                            unsigned m = mm[j];
                            if (!(m & 1u)) out[0 * NE + n] = sc[j];
                            if (!(m & 2u)) out[1 * NE + n] = sc[j];
                            if (!(m & 4u)) out[2 * NE + n] = sc[j];
                            if (!(m & 8u)) out[3 * NE + n] = sc[j];
                        }
                    }
                }
                __syncwarp();
            } else {
                // ---- active (b,n): full [h, te] @ sW1 ----
                int p = __ldcg(&g_nlist[w - nBg]);
                int n = p >> 2, b = p & 3;
                int slot = __ldcg(&g_slotmap[b * NE + n]) - 1;
                sm.s.te[wl][lane]      = __ldcg(&g_h[slot * DIM + lane]);
                sm.s.te[wl][lane + 32] = __ldcg(&g_h[slot * DIM + lane + 32]);
                sm.s.te[wl][64 + lane] = __ldg(&ent[n * DIM + lane]);
                sm.s.te[wl][96 + lane] = __ldg(&ent[n * DIM + lane + 32]);
                __syncwarp();
                float s0 = rb0, s1 = rb1;
                #pragma unroll 8
                for (int k = 0; k < 2 * DIM; k++) {
                    float xk = sm.s.te[wl][k];
                    float2 wv = sm.s.w[k * 32 + lane];
                    s0 = fmaf(xk, wv.x, s0);
                    s1 = fmaf(xk, wv.y, s1);
                }
                float a = fmaxf(s0, 0.f) * rv0 + fmaxf(s1, 0.f) * rv1;
                #pragma unroll
                for (int o = 16; o > 0; o >>= 1) a += __shfl_xor_sync(FULL, a, o);
                if (lane == 0) out[b * NE + n] = a + b2;
                __syncwarp();
            }
        }
    }

    // ---------------- final arrive-only barrier + state reset ----------------
    __syncthreads();
    if (tid == 0) {
        __threadfence();
        atomicAdd(&g_bar[15], 1u);
        if (bid == 0) {
            while (*(volatile unsigned int*)&g_bar[15] < (unsigned)nb) __nanosleep(32);
            #pragma unroll
            for (int i = 0; i < 16; i++) g_bar[i] = 0u;
            #pragma unroll
            for (int i = 0; i < 8; i++) g_cnt[i] = 0;
        }
    }
}

extern "C" void kernel_launch(void* const* d_in, const int* in_sizes, int n_in,
                              void* d_out, int out_size) {
    const float* ent   = (const float*)d_in[0];
    const float* qemb  = (const float*)d_in[1];
    const float* rele  = (const float*)d_in[2];
    const float* msgW  = (const float*)d_in[3];
    const float* gateW = (const float*)d_in[4];
    const float* updW  = (const float*)d_in[5];
    const float* updb  = (const float*)d_in[6];
    const float* lng   = (const float*)d_in[7];
    const float* lnb   = (const float*)d_in[8];
    const float* sW1   = (const float*)d_in[9];
    const float* sb1   = (const float*)d_in[10];
    const float* sW2   = (const float*)d_in[11];
    const float* sb2   = (const float*)d_in[12];
    const int* source  = (const int*)d_in[13];
    const int* qrel    = (const int*)d_in[14];
    const int* esrc    = (const int*)d_in[15];
    const int* etgt    = (const int*)d_in[16];
    const int* erel    = (const int*)d_in[17];
    float* out = (float*)d_out;

    int dev = 0;
    cudaGetDevice(&dev);
    int sms = 0;
    cudaDeviceGetAttribute(&sms, cudaDevAttrMultiProcessorCount, dev);
    int maxb = 0;
    cudaOccupancyMaxActiveBlocksPerMultiprocessor(&maxb, k_all, TPB, 0);
    if (maxb < 1) maxb = 1;
    int grid = sms * maxb;

    k_all<<<grid, TPB>>>(ent, qemb, rele, msgW, gateW, updW, updb, lng, lnb,
                         sW1, sb1, sW2, sb2, source, qrel, esrc, etgt, erel, out);
}

// round 10
// speedup vs baseline: 1.1667x; 1.0131x over previous
#include <cuda_runtime.h>
#include <math.h>

#define NE      50000
#define DIM     64
#define NREL    400
#define NLAYERS 3
#define BS      4
#define NEDGE   400000
#define MAXSLOTS (BS * NE)
#define FULL 0xffffffffu
#define TPB 256
#define WPB (TPB / 32)

// ---------------- persistent device scratch (static, no allocation) ----------
__device__ float        g_h[MAXSLOTS * DIM];
__device__ float        g_agg[MAXSLOTS * DIM];
__device__ int          g_slotmap[BS * NE];      // slot+1, 0 = free, -1 = claiming
__device__ unsigned int g_mask[NE];              // bit b = (b,node) active
__device__ int          g_elist[BS * NEDGE];     // packed (edge<<2)|b
__device__ int          g_nlist[MAXSLOTS];       // packed (node<<2)|b
__device__ int          g_cnt[8];                // 0 slots, 1 nlist, 2+l edges/layer
__device__ unsigned int g_bar[16];               // device barrier counters

struct SMemMsg { float M[DIM * DIM]; float G[DIM * DIM]; float sh[WPB][DIM]; };
struct SMemUpd { float W[2 * DIM * DIM]; float x[WPB][2 * DIM]; };
struct SMemSc  { float2 w[2 * DIM * 32]; float4 te4[WPB][2][DIM]; };  // 32KB+16KB
union SMemAll { SMemMsg m; SMemUpd u; SMemSc s; };

// Grid-wide barrier: grid sized by the occupancy API -> all blocks resident.
__device__ __forceinline__ void gbar(int i) {
    __syncthreads();
    if (threadIdx.x == 0) {
        __threadfence();
        atomicAdd(&g_bar[i], 1u);
        while (*(volatile unsigned int*)&g_bar[i] < gridDim.x) __nanosleep(32);
    }
    __syncthreads();
}

// Warp-aggregated append of active (edge,batch) pairs into g_elist.
__device__ __forceinline__ void push4(int base, const unsigned mm[4], int cslot, int lane) {
    int cnt = __popc(mm[0]) + __popc(mm[1]) + __popc(mm[2]) + __popc(mm[3]);
    int x = cnt;
    #pragma unroll
    for (int o = 1; o < 32; o <<= 1) {
        int y = __shfl_up_sync(FULL, x, o);
        if (lane >= o) x += y;
    }
    int warpTotal = __shfl_sync(FULL, x, 31);
    if (warpTotal == 0) return;
    int basePos = 0;
    if (lane == 31) basePos = atomicAdd(&g_cnt[cslot], warpTotal);
    basePos = __shfl_sync(FULL, basePos, 31);
    int pos = basePos + x - cnt;
    #pragma unroll
    for (int j = 0; j < 4; j++) {
        unsigned m = mm[j];
        while (m) {
            int b = __ffs((int)m) - 1;
            m &= m - 1;
            g_elist[pos++] = ((base + j) << 2) | b;
        }
    }
}

__device__ __forceinline__ void scan_layer(const int* __restrict__ esrc, int layer,
                                           int gwarp, int gwarps, int lane) {
    const int CW = NEDGE / 4 / 32;   // 3125
    for (int cw = gwarp; cw < CW; cw += gwarps) {
        int base = (cw * 32 + lane) * 4;
        int4 e4 = *reinterpret_cast<const int4*>(esrc + base);
        unsigned mm[4];
        mm[0] = __ldcg(&g_mask[e4.x]);
        mm[1] = __ldcg(&g_mask[e4.y]);
        mm[2] = __ldcg(&g_mask[e4.z]);
        mm[3] = __ldcg(&g_mask[e4.w]);
        push4(base, mm, 2 + layer, lane);
    }
}

__global__ void __launch_bounds__(TPB, 2)
k_all(const float* __restrict__ ent, const float* __restrict__ qemb,
      const float* __restrict__ rele, const float* __restrict__ msgW,
      const float* __restrict__ gateW, const float* __restrict__ updW,
      const float* __restrict__ updb, const float* __restrict__ lng,
      const float* __restrict__ lnb, const float* __restrict__ sW1,
      const float* __restrict__ sb1, const float* __restrict__ sW2,
      const float* __restrict__ sb2, const int* __restrict__ source,
      const int* __restrict__ qrel, const int* __restrict__ esrc,
      const int* __restrict__ etgt, const int* __restrict__ erel,
      float* __restrict__ out) {
    __shared__ SMemAll sm;
    const int tid  = threadIdx.x;
    const int lane = tid & 31;
    const int wl   = tid >> 5;
    const int bid  = blockIdx.x;
    const int nb   = gridDim.x;
    const int gthreads = nb * TPB;
    const int gwarps   = gthreads >> 5;
    const int gwarp    = bid * WPB + wl;
    const int gt       = bid * TPB + tid;

    // ---------------- P0: zero slotmap+mask  ∥  scan layer-0 ----------------
    {
        int4 z = make_int4(0, 0, 0, 0);
        for (int j = gt; j < BS * NE / 4; j += gthreads) ((int4*)g_slotmap)[j] = z;
        for (int j = gt; j < NE / 4; j += gthreads) ((int4*)g_mask)[j] = z;

        int s0 = __ldg(&source[0]), s1 = __ldg(&source[1]);
        int s2 = __ldg(&source[2]), s3 = __ldg(&source[3]);
        const int CW = NEDGE / 4 / 32;
        for (int cw = gwarp; cw < CW; cw += gwarps) {
            int base = (cw * 32 + lane) * 4;
            int4 e4 = *reinterpret_cast<const int4*>(esrc + base);
            unsigned mm[4];
            mm[0] = (unsigned)(e4.x == s0) | ((unsigned)(e4.x == s1) << 1) |
                    ((unsigned)(e4.x == s2) << 2) | ((unsigned)(e4.x == s3) << 3);
            mm[1] = (unsigned)(e4.y == s0) | ((unsigned)(e4.y == s1) << 1) |
                    ((unsigned)(e4.y == s2) << 2) | ((unsigned)(e4.y == s3) << 3);
            mm[2] = (unsigned)(e4.z == s0) | ((unsigned)(e4.z == s1) << 1) |
                    ((unsigned)(e4.z == s2) << 2) | ((unsigned)(e4.z == s3) << 3);
            mm[3] = (unsigned)(e4.w == s0) | ((unsigned)(e4.w == s1) << 1) |
                    ((unsigned)(e4.w == s2) << 2) | ((unsigned)(e4.w == s3) << 3);
            push4(base, mm, 2, lane);
        }
    }
    gbar(0);

    // ---------------- P1: seed the BS source nodes (block 0 only) -------------
    if (bid == 0) {
        if (wl < BS) {
            int n = __ldg(&source[wl]);
            int r = __ldg(&qrel[wl]);
            if (lane == 0) {
                g_slotmap[wl * NE + n] = wl + 1;
                atomicOr(&g_mask[n], 1u << wl);
                g_nlist[wl] = (n << 2) | wl;
            }
            g_h[wl * DIM + lane]      = __ldg(&ent[n * DIM + lane])      + __ldg(&qemb[r * DIM + lane]);
            g_h[wl * DIM + lane + 32] = __ldg(&ent[n * DIM + lane + 32]) + __ldg(&qemb[r * DIM + lane + 32]);
            g_agg[wl * DIM + lane] = 0.f;
            g_agg[wl * DIM + lane + 32] = 0.f;
        }
        if (tid == 0) { g_cnt[0] = BS; g_cnt[1] = BS; }
    }
    gbar(1);

    // ---------------- per-layer: msg, then (scan next + update) ----------------
    for (int l = 0; l < NLAYERS; l++) {
        // ---- msg(l): claim target slots + matvec + atomic scatter ----
        {
            int total = __ldcg(&g_cnt[2 + l]);
            int pb = min(nb, (total + WPB - 1) / WPB);
            if (bid < pb) {
                for (int i = tid; i < DIM * DIM; i += TPB) {
                    sm.m.M[i] = __ldg(&msgW[l * DIM * DIM + i]);
                    sm.m.G[i] = __ldg(&gateW[l * DIM * DIM + i]);
                }
                __syncthreads();
                for (int idx = bid * WPB + wl; idx < total; idx += pb * WPB) {
                    int p = __ldcg(&g_elist[idx]);
                    int e = p >> 2, b = p & 3;
                    int s = __ldg(&esrc[e]), t = __ldg(&etgt[e]), r = __ldg(&erel[e]);
                    int ss = __ldcg(&g_slotmap[b * NE + s]) - 1;

                    int* sp = &g_slotmap[b * NE + t];
                    int cur;
                    if (lane == 0) cur = atomicCAS(sp, 0, -1);
                    cur = __shfl_sync(FULL, cur, 0);
                    int ts;
                    if (cur == 0) {                       // claimed: init slot
                        int slot;
                        if (lane == 0) slot = atomicAdd(&g_cnt[0], 1);
                        slot = __shfl_sync(FULL, slot, 0);
                        g_h[slot * DIM + lane] = 0.f;       g_h[slot * DIM + lane + 32] = 0.f;
                        g_agg[slot * DIM + lane] = 0.f;     g_agg[slot * DIM + lane + 32] = 0.f;
                        __syncwarp();
                        __threadfence();
                        if (lane == 0) {
                            int ni = atomicAdd(&g_cnt[1], 1);
                            g_nlist[ni] = (t << 2) | b;
                            atomicOr(&g_mask[t], 1u << b);  // activation for next scan
                            atomicExch(sp, slot + 1);       // publish
                        }
                        ts = slot;
                    } else if (cur > 0) {
                        ts = cur - 1;
                    } else {
                        if (lane == 0) { do { cur = atomicAdd(sp, 0); } while (cur <= 0); }
                        cur = __shfl_sync(FULL, cur, 0);
                        ts = cur - 1;
                    }

                    sm.m.sh[wl][lane]      = __ldcg(&g_h[ss * DIM + lane]);
                    sm.m.sh[wl][lane + 32] = __ldcg(&g_h[ss * DIM + lane + 32]);
                    __syncwarp();
                    float m0 = 0.f, m1 = 0.f, q0 = 0.f, q1 = 0.f;
                    #pragma unroll 8
                    for (int k = 0; k < DIM; k++) {
                        float hk = sm.m.sh[wl][k];
                        m0 = fmaf(hk, sm.m.M[k * DIM + lane],      m0);
                        m1 = fmaf(hk, sm.m.M[k * DIM + lane + 32], m1);
                        q0 = fmaf(hk, sm.m.G[k * DIM + lane],      q0);
                        q1 = fmaf(hk, sm.m.G[k * DIM + lane + 32], q1);
                    }
                    const float* rr = rele + (size_t)(l * NREL + r) * DIM;
                    float v0 = __ldg(&rr[lane])      * m0 * (1.f / (1.f + expf(-q0)));
                    float v1 = __ldg(&rr[lane + 32]) * m1 * (1.f / (1.f + expf(-q1)));
                    atomicAdd(&g_agg[ts * DIM + lane],      v0);
                    atomicAdd(&g_agg[ts * DIM + lane + 32], v1);
                    __syncwarp();
                }
            }
        }
        gbar(2 + 2 * l);

        // ---- scan(l+1) over all blocks (independent of update) ----
        if (l + 1 < NLAYERS) scan_layer(esrc, l + 1, gwarp, gwarps, lane);

        // ---- update(l): h = LN(h + relu([h,agg]@W + b)) over nlist ----
        {
            int total = __ldcg(&g_cnt[1]);
            int pb = min(nb, (total + WPB - 1) / WPB);
            if (bid < pb) {
                for (int i = tid; i < 2 * DIM * DIM; i += TPB)
                    sm.u.W[i] = __ldg(&updW[l * 2 * DIM * DIM + i]);
                __syncthreads();
                float ub0 = __ldg(&updb[l * DIM + lane]), ub1 = __ldg(&updb[l * DIM + lane + 32]);
                float lg0 = __ldg(&lng[l * DIM + lane]),  lg1 = __ldg(&lng[l * DIM + lane + 32]);
                float lb0 = __ldg(&lnb[l * DIM + lane]),  lb1 = __ldg(&lnb[l * DIM + lane + 32]);
                for (int idx = bid * WPB + wl; idx < total; idx += pb * WPB) {
                    int p = __ldcg(&g_nlist[idx]);
                    int n = p >> 2, b = p & 3;
                    int slot = __ldcg(&g_slotmap[b * NE + n]) - 1;
                    float h0 = __ldcg(&g_h[slot * DIM + lane]);
                    float h1 = __ldcg(&g_h[slot * DIM + lane + 32]);
                    float a0 = __ldcg(&g_agg[slot * DIM + lane]);
                    float a1 = __ldcg(&g_agg[slot * DIM + lane + 32]);
                    sm.u.x[wl][lane] = h0;      sm.u.x[wl][lane + 32] = h1;
                    sm.u.x[wl][64 + lane] = a0; sm.u.x[wl][96 + lane] = a1;
                    __syncwarp();
                    float u0 = ub0, u1 = ub1;
                    #pragma unroll 8
                    for (int k = 0; k < 2 * DIM; k++) {
                        float xk = sm.u.x[wl][k];
                        u0 = fmaf(xk, sm.u.W[k * DIM + lane],      u0);
                        u1 = fmaf(xk, sm.u.W[k * DIM + lane + 32], u1);
                    }
                    u0 = fmaxf(u0, 0.f); u1 = fmaxf(u1, 0.f);
                    float x0 = h0 + u0, x1 = h1 + u1;
                    float sums = x0 + x1;
                    #pragma unroll
                    for (int o = 16; o > 0; o >>= 1) sums += __shfl_xor_sync(FULL, sums, o);
                    float mean = sums * (1.f / 64.f);
                    float d0 = x0 - mean, d1 = x1 - mean;
                    float v = d0 * d0 + d1 * d1;
                    #pragma unroll
                    for (int o = 16; o > 0; o >>= 1) v += __shfl_xor_sync(FULL, v, o);
                    float inv = rsqrtf(v * (1.f / 64.f) + 1e-5f);
                    g_h[slot * DIM + lane]      = d0 * inv * lg0 + lb0;
                    g_h[slot * DIM + lane + 32] = d1 * inv * lg1 + lb1;
                    g_agg[slot * DIM + lane] = 0.f;
                    g_agg[slot * DIM + lane + 32] = 0.f;
                    __syncwarp();
                }
            }
        }
        gbar(3 + 2 * l);
    }

    // ---------------- score ----------------
    {
        for (int i = tid; i < 2 * DIM * 32; i += TPB) {
            int k = i >> 5, j = i & 31;
            sm.s.w[i] = make_float2(__ldg(&sW1[k * DIM + j]), __ldg(&sW1[k * DIM + j + 32]));
        }
        __syncthreads();
        float rb0 = __ldg(&sb1[lane]), rb1 = __ldg(&sb1[lane + 32]);
        float rv0 = __ldg(&sW2[lane]), rv1 = __ldg(&sW2[lane + 32]);
        float b2 = __ldg(&sb2[0]);
        int nAct = __ldcg(&g_cnt[1]);
        const int nBg = NE / 8;       // 6250
        int W = nBg + nAct;
        float4* teA = sm.s.te4[wl][0];
        float4* teB = sm.s.te4[wl][1];
        for (int w = gwarp; w < W; w += gwarps) {
            if (w < nBg) {
                // ---- background: 8 nodes, h = 0 → only rows [64,128) of sW1 ----
                int n0 = w * 8;
                int4 mload0, mload1;
                if (lane == 0) {
                    mload0 = __ldcg(reinterpret_cast<const int4*>(&g_mask[n0]));
                    mload1 = __ldcg(reinterpret_cast<const int4*>(&g_mask[n0 + 4]));
                }
                float v0 = __ldg(&ent[(n0 + 0) * DIM + lane]);
                float v1 = __ldg(&ent[(n0 + 1) * DIM + lane]);
                float v2 = __ldg(&ent[(n0 + 2) * DIM + lane]);
                float v3 = __ldg(&ent[(n0 + 3) * DIM + lane]);
                float v4 = __ldg(&ent[(n0 + 4) * DIM + lane]);
                float v5 = __ldg(&ent[(n0 + 5) * DIM + lane]);
                float v6 = __ldg(&ent[(n0 + 6) * DIM + lane]);
                float v7 = __ldg(&ent[(n0 + 7) * DIM + lane]);
                float u0 = __ldg(&ent[(n0 + 0) * DIM + lane + 32]);
                float u1 = __ldg(&ent[(n0 + 1) * DIM + lane + 32]);
                float u2 = __ldg(&ent[(n0 + 2) * DIM + lane + 32]);
                float u3 = __ldg(&ent[(n0 + 3) * DIM + lane + 32]);
                float u4 = __ldg(&ent[(n0 + 4) * DIM + lane + 32]);
                float u5 = __ldg(&ent[(n0 + 5) * DIM + lane + 32]);
                float u6 = __ldg(&ent[(n0 + 6) * DIM + lane + 32]);
                float u7 = __ldg(&ent[(n0 + 7) * DIM + lane + 32]);
                // transposed staging: te*[k] = 4 nodes' column-k values
                // inner loop reads are broadcast LDS.128 (1 wavefront each)
                teA[lane]      = make_float4(v0, v1, v2, v3);
                teA[lane + 32] = make_float4(u0, u1, u2, u3);
                teB[lane]      = make_float4(v4, v5, v6, v7);
                teB[lane + 32] = make_float4(u4, u5, u6, u7);
                __syncwarp();
                float s0[8], s1[8];
                #pragma unroll
                for (int j = 0; j < 8; j++) { s0[j] = rb0; s1[j] = rb1; }
                #pragma unroll 4
                for (int k = 0; k < DIM; k++) {
                    float2 wv = sm.s.w[(DIM + k) * 32 + lane];
                    float4 a = teA[k];
                    float4 b = teB[k];
                    s0[0] = fmaf(a.x, wv.x, s0[0]); s1[0] = fmaf(a.x, wv.y, s1[0]);
                    s0[1] = fmaf(a.y, wv.x, s0[1]); s1[1] = fmaf(a.y, wv.y, s1[1]);
                    s0[2] = fmaf(a.z, wv.x, s0[2]); s1[2] = fmaf(a.z, wv.y, s1[2]);
                    s0[3] = fmaf(a.w, wv.x, s0[3]); s1[3] = fmaf(a.w, wv.y, s1[3]);
                    s0[4] = fmaf(b.x, wv.x, s0[4]); s1[4] = fmaf(b.x, wv.y, s1[4]);
                    s0[5] = fmaf(b.y, wv.x, s0[5]); s1[5] = fmaf(b.y, wv.y, s1[5]);
                    s0[6] = fmaf(b.z, wv.x, s0[6]); s1[6] = fmaf(b.z, wv.y, s1[6]);
                    s0[7] = fmaf(b.w, wv.x, s0[7]); s1[7] = fmaf(b.w, wv.y, s1[7]);
                }
                float sc[8];
                #pragma unroll
                for (int j = 0; j < 8; j++) {
                    float a = fmaxf(s0[j], 0.f) * rv0 + fmaxf(s1[j], 0.f) * rv1;
                    #pragma unroll
                    for (int o = 16; o > 0; o >>= 1) a += __shfl_xor_sync(FULL, a, o);
                    sc[j] = a + b2;
                }
                if (lane == 0) {
                    unsigned any = (unsigned)(mload0.x | mload0.y | mload0.z | mload0.w |
                                              mload1.x | mload1.y | mload1.z | mload1.w);
                    if (any == 0u) {
                        // fast path: all 8 nodes background in all batches -> 8x STG.128
                        float4 va = make_float4(sc[0], sc[1], sc[2], sc[3]);
                        float4 vb = make_float4(sc[4], sc[5], sc[6], sc[7]);
                        #pragma unroll
                        for (int b = 0; b < BS; b++) {
                            *reinterpret_cast<float4*>(&out[b * NE + n0])     = va;
                            *reinterpret_cast<float4*>(&out[b * NE + n0 + 4]) = vb;
                        }
                    } else {
                        unsigned mm[8];
                        mm[0] = (unsigned)mload0.x; mm[1] = (unsigned)mload0.y;
                        mm[2] = (unsigned)mload0.z; mm[3] = (unsigned)mload0.w;
                        mm[4] = (unsigned)mload1.x; mm[5] = (unsigned)mload1.y;
                        mm[6] = (unsigned)mload1.z; mm[7] = (unsigned)mload1.w;
                        #pragma unroll
                        for (int j = 0; j < 8; j++) {
                            int n = n0 + j;
                            unsigned m = mm[j];
                            if (!(m & 1u)) out[0 * NE + n] = sc[j];
                            if (!(m & 2u)) out[1 * NE + n] = sc[j];
                            if (!(m & 4u)) out[2 * NE + n] = sc[j];
                            if (!(m & 8u)) out[3 * NE + n] = sc[j];
                        }
                    }
                }
                __syncwarp();
            } else {
                // ---- active (b,n): full [h, te] @ sW1 ----
                int p = __ldcg(&g_nlist[w - nBg]);
                int n = p >> 2, b = p & 3;
                int slot = __ldcg(&g_slotmap[b * NE + n]) - 1;
                float* tep = reinterpret_cast<float*>(teA);   // scratch (128 floats)
                tep[lane]      = __ldcg(&g_h[slot * DIM + lane]);
                tep[lane + 32] = __ldcg(&g_h[slot * DIM + lane + 32]);
                tep[64 + lane] = __ldg(&ent[n * DIM + lane]);
                tep[96 + lane] = __ldg(&ent[n * DIM + lane + 32]);
                __syncwarp();
                float s0 = rb0, s1 = rb1;
                #pragma unroll 8
                for (int k = 0; k < 2 * DIM; k++) {
                    float xk = tep[k];
                    float2 wv = sm.s.w[k * 32 + lane];
                    s0 = fmaf(xk, wv.x, s0);
                    s1 = fmaf(xk, wv.y, s1);
                }
                float a = fmaxf(s0, 0.f) * rv0 + fmaxf(s1, 0.f) * rv1;
                #pragma unroll
                for (int o = 16; o > 0; o >>= 1) a += __shfl_xor_sync(FULL, a, o);
                if (lane == 0) out[b * NE + n] = a + b2;
                __syncwarp();
            }
        }
    }

    // ---------------- final arrive-only barrier + state reset ----------------
    __syncthreads();
    if (tid == 0) {
        __threadfence();
        atomicAdd(&g_bar[15], 1u);
        if (bid == 0) {
            while (*(volatile unsigned int*)&g_bar[15] < (unsigned)nb) __nanosleep(32);
            #pragma unroll
            for (int i = 0; i < 16; i++) g_bar[i] = 0u;
            #pragma unroll
            for (int i = 0; i < 8; i++) g_cnt[i] = 0;
        }
    }
}

extern "C" void kernel_launch(void* const* d_in, const int* in_sizes, int n_in,
                              void* d_out, int out_size) {
    const float* ent   = (const float*)d_in[0];
    const float* qemb  = (const float*)d_in[1];
    const float* rele  = (const float*)d_in[2];
    const float* msgW  = (const float*)d_in[3];
    const float* gateW = (const float*)d_in[4];
    const float* updW  = (const float*)d_in[5];
    const float* updb  = (const float*)d_in[6];
    const float* lng   = (const float*)d_in[7];
    const float* lnb   = (const float*)d_in[8];
    const float* sW1   = (const float*)d_in[9];
    const float* sb1   = (const float*)d_in[10];
    const float* sW2   = (const float*)d_in[11];
    const float* sb2   = (const float*)d_in[12];
    const int* source  = (const int*)d_in[13];
    const int* qrel    = (const int*)d_in[14];
    const int* esrc    = (const int*)d_in[15];
    const int* etgt    = (const int*)d_in[16];
    const int* erel    = (const int*)d_in[17];
    float* out = (float*)d_out;

    int dev = 0;
    cudaGetDevice(&dev);
    int sms = 0;
    cudaDeviceGetAttribute(&sms, cudaDevAttrMultiProcessorCount, dev);
    int maxb = 0;
    cudaOccupancyMaxActiveBlocksPerMultiprocessor(&maxb, k_all, TPB, 0);
    if (maxb < 1) maxb = 1;
    int grid = sms * maxb;

    k_all<<<grid, TPB>>>(ent, qemb, rele, msgW, gateW, updW, updb, lng, lnb,
                         sW1, sb1, sW2, sb2, source, qrel, esrc, etgt, erel, out);
}